// round 1
// baseline (speedup 1.0000x reference)
#include <cuda_runtime.h>

// Fused anti-aliased max-pool:
//   x(32,64,112,112) --up2+FIR7(sep, pad3)--> 224x224
//     --maxpool 5x5 s1 pad1--> 222x222 --FIR7(sep, pad3)+down4--> 56x56
//
// One CTA = one (n,c) image x one 8-row output strip. All intermediates in smem.

#define TI     8            // output rows per CTA strip
#define NRIN   22           // input rows needed: 2*TI+6
#define NRA    39           // up-FIR rows needed: 4*TI+7   (u = u0..u0+38)
#define NRM    35           // maxpool rows needed: 4*TI+3  (r = r0..r0+34)
#define WIN    112
#define WA     118          // A cols padded: w in [-3,114] -> cw = w+3
#define WB     224
#define WC     222
#define HOUT   56
#define WOUT   56
#define NTHREADS 256

// smem layout (floats):
#define OFF_IN  0                        // 22*112 = 2464   (reused by sD: 8*222=1776)
#define OFF_A   (OFF_IN + NRIN*WIN)      // 39*118 = 4602
#define OFF_B   (OFF_A + NRA*WA)         // 39*224 = 8736   (reused by sC: 35*222=7770)
#define OFF_M   (OFF_B + NRA*WB)         // 35*224 = 7840
#define SMEM_FLOATS (OFF_M + NRM*WB)     // 23642 floats = 94568 bytes

__global__ void __launch_bounds__(NTHREADS, 2)
aamaxpool_fused_kernel(const float* __restrict__ x,
                       const float* __restrict__ fpre,
                       const float* __restrict__ fpost,
                       float* __restrict__ out)
{
    extern __shared__ float sm[];
    float* sIn = sm + OFF_IN;
    float* sA  = sm + OFF_A;
    float* sB  = sm + OFF_B;
    float* sM  = sm + OFF_M;
    float* sC  = sB;     // col-max result reuses B storage (B dead after row-max)
    float* sD  = sIn;    // stage-3 H-FIR result reuses input storage

    const int nc  = blockIdx.y;
    const int i0  = blockIdx.x * TI;       // first output row of strip
    const int tid = threadIdx.x;

    float f[7], g[7];
#pragma unroll
    for (int t = 0; t < 7; t++) { f[t] = __ldg(fpre + t); g[t] = __ldg(fpost + t); }

    const float* xin = x + (size_t)nc * (WIN * WIN);
    const int in_row0 = 2 * i0 - 3;        // first input row needed
    const int u0 = 4 * i0 - 4;             // first up-FIR (224-grid) row needed
    const float NEG_INF = __int_as_float(0xff800000);

    // ---- load input strip (zero-pad rows outside [0,111]) ----
    for (int idx = tid; idx < NRIN * WIN; idx += NTHREADS) {
        int lr = idx / WIN, w = idx - lr * WIN;
        int gr = in_row0 + lr;
        sIn[idx] = (gr >= 0 && gr < 112) ? xin[gr * WIN + w] : 0.f;
    }
    __syncthreads();

    // ---- stage A: up-2 + FIR7 along H (polyphase). A[lu][cw], cw=w+3 ----
    for (int idx = tid; idx < NRA * WA; idx += NTHREADS) {
        int lu = idx / WA, cw = idx - lu * WA;
        int u = u0 + lu;
        int w = cw - 3;
        float v = 0.f;
        if (u >= 0 && u <= 223 && w >= 0 && w < 112) {
            if ((u & 1) == 0) {            // even phase: taps f1,f3,f5
                int lm = (u >> 1) - in_row0;
                v = f[1] * sIn[(lm - 1) * WIN + w]
                  + f[3] * sIn[ lm      * WIN + w]
                  + f[5] * sIn[(lm + 1) * WIN + w];
            } else {                       // odd phase: taps f0,f2,f4,f6
                int lm = ((u - 3) >> 1) - in_row0;
                v = f[0] * sIn[ lm      * WIN + w]
                  + f[2] * sIn[(lm + 1) * WIN + w]
                  + f[4] * sIn[(lm + 2) * WIN + w]
                  + f[6] * sIn[(lm + 3) * WIN + w];
            }
        }
        sA[idx] = v;
    }
    __syncthreads();

    // ---- stage B: up-2 + FIR7 along W. B[lu][v], v in [0,223]. ----
    // invalid global rows -> -inf so row-max ignores them (maxpool -inf pad).
    for (int idx = tid; idx < NRA * WB; idx += NTHREADS) {
        int lu = idx / WB, v = idx - lu * WB;
        int u = u0 + lu;
        float val;
        if (u < 0 || u > 223) {
            val = NEG_INF;
        } else {
            const float* Ar = sA + lu * WA + 3;   // Ar[w] == A[lu][w]
            if ((v & 1) == 0) {
                int w = v >> 1;
                val = f[1] * Ar[w - 1] + f[3] * Ar[w] + f[5] * Ar[w + 1];
            } else {
                int w = (v - 3) >> 1;
                val = f[0] * Ar[w] + f[2] * Ar[w + 1] + f[4] * Ar[w + 2] + f[6] * Ar[w + 3];
            }
        }
        sB[idx] = val;
    }
    __syncthreads();

    // ---- stage M: 5-row sliding max (stride 1). M[lr][v], r = r0+lr ----
    // r0 = 4*i0-3; B local rows lr..lr+4 correspond to global r-1..r+3.
    for (int idx = tid; idx < NRM * WB; idx += NTHREADS) {
        int lr = idx / WB, v = idx - lr * WB;
        const float* Bc = sB + lr * WB + v;
        float m = Bc[0];
        m = fmaxf(m, Bc[1 * WB]);
        m = fmaxf(m, Bc[2 * WB]);
        m = fmaxf(m, Bc[3 * WB]);
        m = fmaxf(m, Bc[4 * WB]);
        sM[idx] = m;
    }
    __syncthreads();

    // ---- stage C: 5-col sliding max. C[lr][s], s in [0,221] ----
    // window v = s-1..s+3 clamped to [0,223] (clamp duplicates an in-window
    // element, harmless for max).
    for (int idx = tid; idx < NRM * WC; idx += NTHREADS) {
        int lr = idx / WC, s = idx - lr * WC;
        const float* Mr = sM + lr * WB;
        int vlo = (s - 1 < 0) ? 0 : s - 1;
        int vhi = (s + 3 > 223) ? 223 : s + 3;
        float m = Mr[vlo];
        m = fmaxf(m, Mr[s]);
        m = fmaxf(m, Mr[s + 1]);
        m = fmaxf(m, Mr[s + 2]);
        m = fmaxf(m, Mr[vhi]);
        sC[idx] = m;
    }
    __syncthreads();

    // ---- stage D: FIR7 along H of C, sampled at rows 4i (zero-pad outside [0,221]) ----
    for (int idx = tid; idx < TI * WC; idx += NTHREADS) {
        int li = idx / WC, s = idx - li * WC;
        int i = i0 + li;
        float acc = 0.f;
#pragma unroll
        for (int a = 0; a < 7; a++) {
            int rg = 4 * i + a - 3;
            if (rg >= 0 && rg <= 221)
                acc += g[a] * sC[(4 * li + a) * WC + s];
        }
        sD[idx] = acc;
    }
    __syncthreads();

    // ---- stage out: FIR7 along W of D, sampled at cols 4j ----
    float* o = out + (size_t)nc * (HOUT * WOUT) + (size_t)i0 * WOUT;
    for (int idx = tid; idx < TI * WOUT; idx += NTHREADS) {
        int li = idx / WOUT, j = idx - li * WOUT;
        float acc = 0.f;
#pragma unroll
        for (int b = 0; b < 7; b++) {
            int sg = 4 * j + b - 3;
            if (sg >= 0 && sg <= 221)
                acc += g[b] * sD[li * WC + sg];
        }
        o[li * WOUT + j] = acc;
    }
}

extern "C" void kernel_launch(void* const* d_in, const int* in_sizes, int n_in,
                              void* d_out, int out_size)
{
    const float* x     = (const float*)d_in[0];   // (32,64,112,112)
    const float* fpre  = (const float*)d_in[1];   // (7,)
    const float* fpost = (const float*)d_in[2];   // (7,)
    float* out = (float*)d_out;                   // (32,64,56,56)

    const size_t smem_bytes = SMEM_FLOATS * sizeof(float); // 94568
    cudaFuncSetAttribute(aamaxpool_fused_kernel,
                         cudaFuncAttributeMaxDynamicSharedMemorySize,
                         (int)smem_bytes);

    dim3 grid(HOUT / TI, 32 * 64);   // 7 strips x 2048 (n,c) images
    aamaxpool_fused_kernel<<<grid, NTHREADS, smem_bytes>>>(x, fpre, fpost, out);
}

// round 3
// speedup vs baseline: 4.3147x; 4.3147x over previous
#include <cuda_runtime.h>

// Fused AA max-pool: up2+FIR7 -> maxpool5 s1 -> FIR7+down4, all in one kernel.
// One CTA = one (n,c) image x 8-row output strip. Register-streamed stages:
//   stage1: global -> vertical up-FIR (polyphase, 4-reg window) -> sA
//   stage2: horizontal up-FIR (branchless 4-tap) + rolling 5-row max -> sM
//   stage3: 5-col max + vertical down-FIR accumulation (8 reg accs) -> sD
//   stage4: horizontal down-FIR -> out

#define TI   8
#define WIN  112
#define WAS  116   // sA row stride (cols 0..114 used; col = w+1, w in [-1,113])
#define NRA  40    // sA rows stored (u0..u0+39; row 39 unused slack)
#define WMS  224
#define NRM  35
#define WDS  224
#define HOUT 56
#define WOUT 56
#define NTHREADS 224

#define OFF_A 0
#define OFF_M (OFF_A + NRA*WAS)            // 4640
#define OFF_D (OFF_M + NRM*WMS)            // 12480
#define SMEM_FLOATS (OFF_D + TI*WDS)       // 14272 floats = 57088 B -> 4 CTAs/SM

__global__ void __launch_bounds__(NTHREADS, 4)
aamaxpool_fused_kernel(const float* __restrict__ x,
                       const float* __restrict__ fpre,
                       const float* __restrict__ fpost,
                       float* __restrict__ out)
{
    extern __shared__ float sm[];
    float* sA = sm + OFF_A;
    float* sM = sm + OFF_M;
    float* sD = sm + OFF_D;

    const int t  = threadIdx.x;
    const int nc = blockIdx.y;
    const int i0 = blockIdx.x * TI;
    const int in_row0 = 2*i0 - 3;          // first input row of the 23-row window
    const int u0 = 4*i0 - 4;               // first 224-grid row consumed by pooling
    const int r0 = 4*i0 - 3;               // first 222-grid (pool-output) row
    const float NEG_INF = __int_as_float(0xff800000);

    const float f0=__ldg(fpre+0), f1=__ldg(fpre+1), f2=__ldg(fpre+2),
                f3=__ldg(fpre+3), f4=__ldg(fpre+4), f5=__ldg(fpre+5),
                f6=__ldg(fpre+6);
    float g[7];
#pragma unroll
    for (int i = 0; i < 7; i++) g[i] = __ldg(fpost + i);

    const float* xin = x + (size_t)nc * (WIN*WIN);

    // ---- stage 1: vertical up-2 FIR, register-streamed down rows ----
    // m-step q emits rows u=2m (f1,f3,f5 on x0..x2) and u=2m+1 (f0,f2,f4,f6 on x0..x3),
    // m = 2*i0-2+q, window = input rows (in_row0+q .. +q+3).
    if (t < WIN) {
        const float* col = xin + t;
        float x0, x1, x2;
        { int r = in_row0;     x0 = (r>=0 && r<WIN) ? col[r*WIN] : 0.f; }
        { int r = in_row0 + 1; x1 = (r>=0 && r<WIN) ? col[r*WIN] : 0.f; }
        { int r = in_row0 + 2; x2 = (r>=0 && r<WIN) ? col[r*WIN] : 0.f; }
        float* sAc = sA + (t + 1);
#pragma unroll
        for (int q = 0; q < 20; q++) {
            int r = in_row0 + q + 3;
            float x3 = (r>=0 && r<WIN) ? col[r*WIN] : 0.f;
            sAc[(2*q  )*WAS] = f1*x0 + f3*x1 + f5*x2;
            sAc[(2*q+1)*WAS] = f0*x0 + f2*x1 + f4*x2 + f6*x3;
            x0 = x1; x1 = x2; x2 = x3;
        }
    } else if (t < WIN + 3) {
        // zero the halo columns ca in {0, 113, 114}
        int ca = (t == WIN) ? 0 : t;
#pragma unroll
        for (int lu = 0; lu < NRA; lu++) sA[lu*WAS + ca] = 0.f;
    }
    __syncthreads();

    // ---- stage 2: horizontal up-2 FIR (branchless) + rolling 5-row max -> sM ----
    // B[u][v]: both phases read sA cols (v>>1)+0..3; coeffs fixed per thread parity.
    // valid global rows u in [0,224): local lu in [vlo, vhi)
    {
        const int v = t;                    // 224 threads, one B/M column each
        const bool odd = (v & 1);
        const float c0 = odd ? f0 : f1;
        const float c1 = odd ? f2 : f3;
        const float c2 = odd ? f4 : f5;
        const float c3 = odd ? f6 : 0.f;
        const int vlo = (0 - u0) > 0 ? (0 - u0) : 0;       // first valid lu
        const int vhi = (224 - u0) < 39 ? (224 - u0) : 39; // one past last valid lu
        const float* ap = sA + (v >> 1);
        float b0=0.f, b1=0.f, b2=0.f, b3=0.f, b4=0.f;
#pragma unroll
        for (int lu = 0; lu < 39; lu++) {
            const float* a = ap + lu*WAS;
            float bv = c0*a[0] + c1*a[1] + c2*a[2] + c3*a[3];
            bv = (lu >= vlo && lu < vhi) ? bv : NEG_INF;   // -inf pad for maxpool
            b0 = b1; b1 = b2; b2 = b3; b3 = b4; b4 = bv;
            if (lu >= 4)
                sM[(lu-4)*WMS + v] =
                    fmaxf(fmaxf(fmaxf(b0, b1), fmaxf(b2, b3)), b4);
        }
    }
    __syncthreads();

    // ---- stage 3: 5-col max + vertical down-FIR accumulate (8 reg accs) -> sD ----
    if (t < 222) {
        const int s = t;
        const int sm1 = (s > 0)   ? s - 1 : 0;     // clamp dup (max-safe)
        const int sp3 = (s < 221) ? s + 3 : 223;
        const int clo = (0 - r0) > 0 ? (0 - r0) : 0;
        const int chi = (222 - r0) < 35 ? (222 - r0) : 35;
        float d[8] = {0.f,0.f,0.f,0.f,0.f,0.f,0.f,0.f};
#pragma unroll
        for (int lc = 0; lc < 35; lc++) {
            if (lc >= clo && lc < chi) {           // zero-pad of stage-3 FIR
                const float* Mr = sM + lc*WMS;
                float cm = fmaxf(fmaxf(fmaxf(Mr[sm1], Mr[s]),
                                       fmaxf(Mr[s+1], Mr[s+2])), Mr[sp3]);
#pragma unroll
                for (int li = 0; li < 8; li++) {
                    int a = lc - 4*li;
                    if (a >= 0 && a < 7) d[li] += g[a] * cm;
                }
            }
        }
#pragma unroll
        for (int li = 0; li < 8; li++) sD[li*WDS + s] = d[li];
    }
    __syncthreads();

    // ---- stage 4: horizontal down-FIR, write output ----
    float* o = out + (size_t)nc * (HOUT*WOUT) + (size_t)i0 * WOUT;
#pragma unroll
    for (int k = 0; k < 2; k++) {
        int idx = t + k*NTHREADS;               // 0..447 = 8x56
        int li = idx / WOUT, j = idx - li*WOUT;
        const float* Dr = sD + li*WDS;
        float acc = 0.f;
#pragma unroll
        for (int b = 0; b < 7; b++) {
            int sg = 4*j + b - 3;
            if (sg >= 0 && sg < 222) acc += g[b] * Dr[sg];
        }
        o[li*WOUT + j] = acc;
    }
}

extern "C" void kernel_launch(void* const* d_in, const int* in_sizes, int n_in,
                              void* d_out, int out_size)
{
    const float* x     = (const float*)d_in[0];   // (32,64,112,112)
    const float* fpre  = (const float*)d_in[1];   // (7,)
    const float* fpost = (const float*)d_in[2];   // (7,)
    float* out = (float*)d_out;                   // (32,64,56,56)

    const size_t smem_bytes = SMEM_FLOATS * sizeof(float); // 57088
    cudaFuncSetAttribute(aamaxpool_fused_kernel,
                         cudaFuncAttributeMaxDynamicSharedMemorySize,
                         (int)smem_bytes);

    dim3 grid(HOUT / TI, 32 * 64);
    aamaxpool_fused_kernel<<<grid, NTHREADS, smem_bytes>>>(x, fpre, fpost, out);
}

// round 4
// speedup vs baseline: 4.4769x; 1.0376x over previous
#include <cuda_runtime.h>

// Fused AA max-pool: up2+FIR7 -> maxpool5x5 s1 -> FIR7+down4. One CTA = one
// (n,c) image x 8 output rows. Stages:
//  s1: global -> vertical up-FIR (polyphase, streamed) -> sA   [2 row-halves]
//  s2: horizontal up-FIR, parity-shared loads, rolling 5-row max -> sM (+/-inf pads)
//  s3: 8-col vectorized 5-col max (pair tree) + vertical down-FIR -> sD (zero pads)
//  s4: horizontal down-FIR (unconditional taps) -> out

#define TI   8
#define WIN  112
#define WAS  116    // sA: col c at idx c+1, c in [-1,113]; rows 0..39
#define NRA  40
#define WMS  232    // sM: col v at idx v+4, v in [-4,227]; rows 0..34
#define NRM  35
#define WDS  232    // sD: col s at idx s+4
#define HOUT 56
#define WOUT 56
#define NTHREADS 224

#define OFF_A 0
#define OFF_M (NRA*WAS)                    // 4640
#define SMEM_FLOATS (OFF_M + NRM*WMS)      // 12760 floats = 51040 B
#define OFF_D OFF_A                        // sD aliases sA (8*232=1856 <= 4640)

__global__ void __launch_bounds__(NTHREADS, 4)
aamaxpool_fused_kernel(const float* __restrict__ x,
                       const float* __restrict__ fpre,
                       const float* __restrict__ fpost,
                       float* __restrict__ out)
{
    extern __shared__ float sm[];
    float* sA = sm + OFF_A;
    float* sM = sm + OFF_M;
    float* sD = sm + OFF_D;

    const int t  = threadIdx.x;
    const int nc = blockIdx.y;
    const int i0 = blockIdx.x * TI;
    const int in_row0 = 2*i0 - 3;
    const int u0 = 4*i0 - 4;
    const int r0 = 4*i0 - 3;
    const float NEG_INF = __int_as_float(0xff800000);

    const float f0=__ldg(fpre+0), f1=__ldg(fpre+1), f2=__ldg(fpre+2),
                f3=__ldg(fpre+3), f4=__ldg(fpre+4), f5=__ldg(fpre+5),
                f6=__ldg(fpre+6);
    float g[7];
#pragma unroll
    for (int i = 0; i < 7; i++) g[i] = __ldg(fpost + i);

    const float* xin = x + (size_t)nc * (WIN*WIN);

    // ---- stage 1: vertical up-2 FIR (2 row-halves of 10 q-steps each) ----
    {
        const int w = t % WIN;
        const int h = t / WIN;               // 0 or 1
        const int q0 = 10*h;
        const float* col = xin + w;
        const int rb = in_row0 + q0;
        float x0, x1, x2;
        { int r = rb;     x0 = (r>=0 && r<WIN) ? col[r*WIN] : 0.f; }
        { int r = rb + 1; x1 = (r>=0 && r<WIN) ? col[r*WIN] : 0.f; }
        { int r = rb + 2; x2 = (r>=0 && r<WIN) ? col[r*WIN] : 0.f; }
        float* sAc = sA + (2*q0)*WAS + (w + 1);
#pragma unroll
        for (int qq = 0; qq < 10; qq++) {
            int r = rb + qq + 3;
            float x3 = (r>=0 && r<WIN) ? col[r*WIN] : 0.f;
            sAc[(2*qq  )*WAS] = f1*x0 + f3*x1 + f5*x2;
            sAc[(2*qq+1)*WAS] = f0*x0 + f2*x1 + f4*x2 + f6*x3;
            x0 = x1; x1 = x2; x2 = x3;
        }
        // halo cols idx {0,113,114} zero, rows 0..39
        for (int idx = t; idx < NRA*3; idx += NTHREADS) {
            int lu = idx / 3, c3 = idx - 3*lu;
            sA[lu*WAS + (c3 == 0 ? 0 : 112 + c3)] = 0.f;
        }
        // sM -inf pads: idx 0..3 (v=-4..-1) and 228..231 (v=224..227), rows 0..34
        for (int idx = t; idx < NRM*8; idx += NTHREADS) {
            int lr = idx >> 3, c = idx & 7;
            sM[lr*WMS + (c < 4 ? c : 224 + c)] = NEG_INF;
        }
    }
    __syncthreads();

    // ---- stage 2: horizontal up-2 FIR (parity-shared) + rolling 5-row max ----
    {
        const int w = t % WIN;               // output cols v=2w, 2w+1
        const int h = t / WIN;
        const int lu_beg = h ? 17 : 0;
        const int lu_end = h ? 39 : 21;
        const int emit0  = h ? 21 : 4;       // first lu that emits (lr = lu-4)
        const int vlo = (0 - u0) > 0 ? (0 - u0) : 0;
        const int vhi = (224 - u0) < 39 ? (224 - u0) : 39;
        const float* ap = sA + w;            // a[k] = A[w-1+k]
        float e0=0,e1=0,e2=0,e3=0,e4=0;      // even-col rolling window
        float o0=0,o1=0,o2=0,o3=0,o4=0;      // odd-col rolling window
        float* mrow = sM + 2*w + 4;
#pragma unroll
        for (int lu = 0; lu < 22; lu++) {
            int LU = lu + lu_beg;
            if (LU >= lu_end) break;
            const float* a = ap + LU*WAS;
            float a0 = a[0], a1 = a[1], a2 = a[2], a3 = a[3];
            float be = f1*a0 + f3*a1 + f5*a2;
            float bo = f0*a0 + f2*a1 + f4*a2 + f6*a3;
            bool valid = (LU >= vlo) && (LU < vhi);
            be = valid ? be : NEG_INF;
            bo = valid ? bo : NEG_INF;
            e0=e1; e1=e2; e2=e3; e3=e4; e4=be;
            o0=o1; o1=o2; o2=o3; o3=o4; o4=bo;
            if (LU >= emit0) {
                float me = fmaxf(fmaxf(fmaxf(e0,e1), fmaxf(e2,e3)), e4);
                float mo = fmaxf(fmaxf(fmaxf(o0,o1), fmaxf(o2,o3)), o4);
                float2 mm = make_float2(me, mo);
                *reinterpret_cast<float2*>(mrow + (LU - 4)*WMS) = mm;
            }
        }
    }
    __syncthreads();

    // ---- stage 3: 8-col 5-window max (pair tree) + vertical down-FIR -> sD ----
    {
        const int q  = t % 28;               // cols s = 8q .. 8q+7
        const int li = t / 28;               // output row 0..7
        const float* base = sM + 8*q;        // addr of v = 8q-4
        float d[8] = {0,0,0,0,0,0,0,0};
#pragma unroll
        for (int a = 0; a < 7; a++) {
            const int lc = 4*li + a;
            const int r  = r0 + lc;
            const float* Mr = base + lc*WMS;
            float4 m0 = *reinterpret_cast<const float4*>(Mr);      // v 8q-4..-1
            float4 m1 = *reinterpret_cast<const float4*>(Mr + 4);  // v 8q..+3
            float4 m2 = *reinterpret_cast<const float4*>(Mr + 8);  // v 8q+4..+7
            float4 m3 = *reinterpret_cast<const float4*>(Mr + 12); // v 8q+8..+11
            float pm1 = fmaxf(m0.w, m1.x);
            float p0 = fmaxf(m1.x, m1.y), p1 = fmaxf(m1.y, m1.z);
            float p2 = fmaxf(m1.z, m1.w), p3 = fmaxf(m1.w, m2.x);
            float p4 = fmaxf(m2.x, m2.y), p5 = fmaxf(m2.y, m2.z);
            float p6 = fmaxf(m2.z, m2.w), p7 = fmaxf(m2.w, m3.x);
            float p8 = fmaxf(m3.x, m3.y);
            float w0 = fmaxf(fmaxf(pm1, p1), m1.w);
            float w1 = fmaxf(fmaxf(p0, p2), m2.x);
            float w2 = fmaxf(fmaxf(p1, p3), m2.y);
            float w3 = fmaxf(fmaxf(p2, p4), m2.z);
            float w4 = fmaxf(fmaxf(p3, p5), m2.w);
            float w5 = fmaxf(fmaxf(p4, p6), m3.x);
            float w6 = fmaxf(fmaxf(p5, p7), m3.y);
            float w7 = fmaxf(fmaxf(p6, p8), m3.z);
            if (r >= 0 && r < 222) {
                float ga = g[a];
                d[0] += ga*w0; d[1] += ga*w1; d[2] += ga*w2; d[3] += ga*w3;
                d[4] += ga*w4; d[5] += ga*w5; d[6] += ga*w6; d[7] += ga*w7;
            }
        }
        if (q == 27) { d[6] = 0.f; d[7] = 0.f; }   // cols 222,223 beyond C width
        float* Dp = sD + li*WDS + 8*q + 4;
        *reinterpret_cast<float4*>(Dp)     = make_float4(d[0], d[1], d[2], d[3]);
        *reinterpret_cast<float4*>(Dp + 4) = make_float4(d[4], d[5], d[6], d[7]);
        // left zero pads of sD (idx 0..3 per row)
        if (t < 32) sD[(t >> 2)*WDS + (t & 3)] = 0.f;
    }
    __syncthreads();

    // ---- stage 4: horizontal down-FIR (unconditional), write output ----
    float* o = out + (size_t)nc * (HOUT*WOUT) + (size_t)i0 * WOUT;
#pragma unroll
    for (int k = 0; k < 2; k++) {
        int idx = t + k*NTHREADS;            // 0..447 = 8x56
        int li = idx / WOUT, j = idx - li*WOUT;
        const float* Dr = sD + li*WDS + 4*j + 1;   // sg=4j-3 at idx 4j+1
        float acc = g[0]*Dr[0] + g[1]*Dr[1] + g[2]*Dr[2] + g[3]*Dr[3]
                  + g[4]*Dr[4] + g[5]*Dr[5] + g[6]*Dr[6];
        o[li*WOUT + j] = acc;
    }
}

extern "C" void kernel_launch(void* const* d_in, const int* in_sizes, int n_in,
                              void* d_out, int out_size)
{
    const float* x     = (const float*)d_in[0];   // (32,64,112,112)
    const float* fpre  = (const float*)d_in[1];   // (7,)
    const float* fpost = (const float*)d_in[2];   // (7,)
    float* out = (float*)d_out;                   // (32,64,56,56)

    const size_t smem_bytes = SMEM_FLOATS * sizeof(float); // 51040
    cudaFuncSetAttribute(aamaxpool_fused_kernel,
                         cudaFuncAttributeMaxDynamicSharedMemorySize,
                         (int)smem_bytes);

    dim3 grid(HOUT / TI, 32 * 64);
    aamaxpool_fused_kernel<<<grid, NTHREADS, smem_bytes>>>(x, fpre, fpost, out);
}

// round 5
// speedup vs baseline: 6.7584x; 1.5096x over previous
#include <cuda_runtime.h>
#include <cuda_fp16.h>

// Fused AA max-pool: up2+FIR7 -> maxpool5x5 s1 -> FIR7+down4.
// One CTA = TWO (n,c) images x 8 output rows.
//  s1: global -> vertical up-FIR (polyphase stream) -> sA (fp32)
//  s2: horizontal up-FIR + rolling 5-row max -> sM (half2, col-pair packed)
//  s3: SIMD 5-col max (hmax2/prmt) + vertical down-FIR (fp32, li-pairs) -> sD
//  s4: horizontal down-FIR (float4 loads) -> out

#define TI   8
#define WIN  112
#define WAS  116                 // sA: col c at idx c+1 (c in [-1,113])
#define NRA  40
#define A_FLOATS (NRA*WAS)       // 4640
#define WMW  120                 // sM row stride in half2 words; cols (2j-4,2j-3) at word j
#define NRM  35
#define M_WORDS (NRM*WMW)        // 4200
#define WDS  232                 // sD: col s at idx s+4
#define HOUT 56
#define WOUT 56
#define NTHREADS 224

#define OFF_A 0                                  // 2 images: 2*4640 floats
#define OFF_M (2*A_FLOATS)                       // 2 images: 2*4200 words
#define SMEM_FLOATS (OFF_M + 2*M_WORDS)          // 17680 * 4B = 70720 B
// sD aliases sA (per image: 8*232=1856 <= 4640)

__device__ __forceinline__ __half2 h2shift(__half2 a, __half2 b) {
    // (hi of a, lo of b)
    unsigned r = __byte_perm(*(unsigned*)&a, *(unsigned*)&b, 0x5432);
    return *(__half2*)&r;
}

__global__ void __launch_bounds__(NTHREADS, 3)
aamaxpool_fused_kernel(const float* __restrict__ x,
                       const float* __restrict__ fpre,
                       const float* __restrict__ fpost,
                       float* __restrict__ out)
{
    extern __shared__ float sm[];
    float*    sA  = sm + OFF_A;
    unsigned* sMh = (unsigned*)(sm + OFF_M);

    const int t  = threadIdx.x;
    const int i0 = blockIdx.x * TI;
    const int nc0 = 2 * blockIdx.y;
    const int in_row0 = 2*i0 - 3;
    const int u0 = 4*i0 - 4;
    const int r0 = 4*i0 - 3;
    const float NEG_INF = __int_as_float(0xff800000);

    const float f0=__ldg(fpre+0), f1=__ldg(fpre+1), f2=__ldg(fpre+2),
                f3=__ldg(fpre+3), f4=__ldg(fpre+4), f5=__ldg(fpre+5),
                f6=__ldg(fpre+6);
    float g[7];
#pragma unroll
    for (int i = 0; i < 7; i++) g[i] = __ldg(fpost + i);

    const int img = t / 112;
    const int tl  = t - 112*img;

    // ---- stage 1: vertical up-2 FIR -> sA (per image), stream 23 rows ----
    {
        const int w = tl;
        const float* col = x + (size_t)(nc0 + img) * (WIN*WIN) + w;
        float* sAi = sA + img * A_FLOATS;
        float x0, x1, x2;
        { int r = in_row0;     x0 = (r>=0 && r<WIN) ? col[r*WIN] : 0.f; }
        { int r = in_row0 + 1; x1 = (r>=0 && r<WIN) ? col[r*WIN] : 0.f; }
        { int r = in_row0 + 2; x2 = (r>=0 && r<WIN) ? col[r*WIN] : 0.f; }
        float* sAc = sAi + (w + 1);
#pragma unroll
        for (int q = 0; q < 20; q++) {
            int r = in_row0 + q + 3;
            float x3 = (r>=0 && r<WIN) ? col[r*WIN] : 0.f;
            sAc[(2*q  )*WAS] = f1*x0 + f3*x1 + f5*x2;
            sAc[(2*q+1)*WAS] = f0*x0 + f2*x1 + f4*x2 + f6*x3;
            x0 = x1; x1 = x2; x2 = x3;
        }
        // sA halo zeros: idx {0,113,114} x 40 rows x 2 imgs = 240
        for (int idx = t; idx < 240; idx += NTHREADS) {
            int im = idx / 120, rem = idx - 120*im;
            int lu = rem / 3, k = rem - 3*lu;
            sA[im*A_FLOATS + lu*WAS + (k == 0 ? 0 : 112 + k)] = 0.f;
        }
        // sM -inf pads: words {0,1,114,115} x 35 rows x 2 imgs = 280
        for (int idx = t; idx < 280; idx += NTHREADS) {
            int im = idx / 140, rem = idx - 140*im;
            int lr = rem >> 2, k = rem & 3;
            sMh[im*M_WORDS + lr*WMW + (k < 2 ? k : 112 + k)] = 0xFC00FC00u;
        }
    }
    __syncthreads();

    // ---- stage 2: horizontal up-2 FIR + rolling 5-row max -> sM (half2) ----
    {
        const int w = tl;                      // emits cols (2w, 2w+1)
        const float* ap = sA + img*A_FLOATS + w;   // a[k] = A[w-1+k]
        unsigned* mcol = sMh + img*M_WORDS + (w + 2);
        const int vlo = (0 - u0) > 0 ? (0 - u0) : 0;
        const int vhi = (224 - u0) < 39 ? (224 - u0) : 39;
        float e0=0,e1=0,e2=0,e3=0,e4=0;
        float o0=0,o1=0,o2=0,o3=0,o4=0;
#pragma unroll
        for (int lu = 0; lu < 39; lu++) {
            const float* a = ap + lu*WAS;
            float a0 = a[0], a1 = a[1], a2 = a[2], a3 = a[3];
            float be = f1*a0 + f3*a1 + f5*a2;
            float bo = f0*a0 + f2*a1 + f4*a2 + f6*a3;
            bool valid = (lu >= vlo) && (lu < vhi);
            be = valid ? be : NEG_INF;
            bo = valid ? bo : NEG_INF;
            e0=e1; e1=e2; e2=e3; e3=e4; e4=be;
            o0=o1; o1=o2; o2=o3; o3=o4; o4=bo;
            if (lu >= 4) {
                float me = fmaxf(fmaxf(fmaxf(e0,e1), fmaxf(e2,e3)), e4);
                float mo = fmaxf(fmaxf(fmaxf(o0,o1), fmaxf(o2,o3)), o4);
                __half2 h = __floats2half2_rn(me, mo);   // lo=me(col 2w), hi=mo
                mcol[(lu - 4)*WMW] = *(unsigned*)&h;
            }
        }
    }
    __syncthreads();

    // ---- stage 3: SIMD 5-col window max + vertical FIR (li-pairs) -> sD ----
    {
        const int q  = tl % 28;                // cols s = 8q..8q+7
        const int lp = tl / 28;                // output rows 2lp, 2lp+1
        const unsigned* Mi = sMh + img*M_WORDS;
        float d0[8] = {0,0,0,0,0,0,0,0};
        float d1[8] = {0,0,0,0,0,0,0,0};
#pragma unroll
        for (int rr = 0; rr < 11; rr++) {
            const int lc = 8*lp + rr;
            const int rg = r0 + lc;
            if (rg >= 0 && rg < 222) {
                const unsigned* Wp = Mi + lc*WMW + 4*q;
                uint4 u0v = *reinterpret_cast<const uint4*>(Wp);
                uint4 u1v = *reinterpret_cast<const uint4*>(Wp + 4);
                __half2 H0=*(__half2*)&u0v.x, H1=*(__half2*)&u0v.y,
                        H2=*(__half2*)&u0v.z, H3=*(__half2*)&u0v.w,
                        H4=*(__half2*)&u1v.x, H5=*(__half2*)&u1v.y,
                        H6=*(__half2*)&u1v.z, H7=*(__half2*)&u1v.w;
                __half2 S1=h2shift(H1,H2), S2=h2shift(H2,H3), S3=h2shift(H3,H4),
                        S4=h2shift(H4,H5), S5=h2shift(H5,H6), S6=h2shift(H6,H7);
                __half2 Z2=__hmax2(H2,S2), Z3=__hmax2(H3,S3), Z4=__hmax2(H4,S4),
                        Z5=__hmax2(H5,S5), Z6=__hmax2(H6,S6);
                __half2 O0=__hmax2(S1,__hmax2(Z2,Z3));   // cols 8q+0,1
                __half2 O1=__hmax2(S2,__hmax2(Z3,Z4));   // cols 8q+2,3
                __half2 O2=__hmax2(S3,__hmax2(Z4,Z5));   // cols 8q+4,5
                __half2 O3=__hmax2(S4,__hmax2(Z5,Z6));   // cols 8q+6,7
                float2 c01=__half22float2(O0), c23=__half22float2(O1),
                       c45=__half22float2(O2), c67=__half22float2(O3);
                float wv[8] = {c01.x,c01.y,c23.x,c23.y,c45.x,c45.y,c67.x,c67.y};
                if (rr <= 6) {
                    float ga = g[rr];
#pragma unroll
                    for (int j = 0; j < 8; j++) d0[j] += ga * wv[j];
                }
                if (rr >= 4) {
                    float gb = g[rr - 4];
#pragma unroll
                    for (int j = 0; j < 8; j++) d1[j] += gb * wv[j];
                }
            }
        }
        if (q == 27) { d0[6]=0.f; d0[7]=0.f; d1[6]=0.f; d1[7]=0.f; }
        float* Di = sA + img*A_FLOATS;     // sD aliases sA
        float* P0 = Di + (2*lp  )*WDS + 8*q + 4;
        float* P1 = Di + (2*lp+1)*WDS + 8*q + 4;
        *reinterpret_cast<float4*>(P0)     = make_float4(d0[0],d0[1],d0[2],d0[3]);
        *reinterpret_cast<float4*>(P0 + 4) = make_float4(d0[4],d0[5],d0[6],d0[7]);
        *reinterpret_cast<float4*>(P1)     = make_float4(d1[0],d1[1],d1[2],d1[3]);
        *reinterpret_cast<float4*>(P1 + 4) = make_float4(d1[4],d1[5],d1[6],d1[7]);
        // sD left zero pads: idx 0..3, 16 rows
        if (t < 64) {
            int im = t >> 5, rem = t & 31;
            sA[im*A_FLOATS + (rem >> 2)*WDS + (rem & 3)] = 0.f;
        }
    }
    __syncthreads();

    // ---- stage 4: horizontal down-FIR (aligned float4 loads) -> out ----
#pragma unroll
    for (int k = 0; k < 4; k++) {
        int gid = t + k*NTHREADS;          // 0..895 = 2 imgs x 8 rows x 56
        int im  = gid / 448;
        int rem = gid - 448*im;
        int li  = rem / 56, j = rem - 56*li;
        const float* Dr = sA + im*A_FLOATS + li*WDS + 4*j;
        float4 va = *reinterpret_cast<const float4*>(Dr);
        float4 vb = *reinterpret_cast<const float4*>(Dr + 4);
        float acc = g[0]*va.y + g[1]*va.z + g[2]*va.w
                  + g[3]*vb.x + g[4]*vb.y + g[5]*vb.z + g[6]*vb.w;
        out[(size_t)(nc0 + im)*(HOUT*WOUT) + (i0 + li)*WOUT + j] = acc;
    }
}

extern "C" void kernel_launch(void* const* d_in, const int* in_sizes, int n_in,
                              void* d_out, int out_size)
{
    const float* x     = (const float*)d_in[0];   // (32,64,112,112)
    const float* fpre  = (const float*)d_in[1];   // (7,)
    const float* fpost = (const float*)d_in[2];   // (7,)
    float* out = (float*)d_out;                   // (32,64,56,56)

    const size_t smem_bytes = SMEM_FLOATS * sizeof(float); // 70720
    cudaFuncSetAttribute(aamaxpool_fused_kernel,
                         cudaFuncAttributeMaxDynamicSharedMemorySize,
                         (int)smem_bytes);

    dim3 grid(HOUT / TI, 32 * 64 / 2);   // 7 strips x 1024 image-pairs
    aamaxpool_fused_kernel<<<grid, NTHREADS, smem_bytes>>>(x, fpre, fpost, out);
}